// round 1
// baseline (speedup 1.0000x reference)
#include <cuda_runtime.h>
#include <cuda_bf16.h>
#include <math.h>

// ---------------- problem constants ----------------
#define NB 2
#define NV 3
#define NC 32
#define ND 48
#define NH 128
#define NW 160
#define NHW (NH*NW)          // 20480

// ---------------- fused kernel tiling ----------------
#define TD 8
#define TH 8
#define TW 32
#define HD (TD+2)            // 10
#define HHs (TH+2)           // 10
#define HWs (TW+2)           // 34
#define NHALO (HD*HHs*HWs)   // 3400
#define SMEM_BYTES (NHALO*16*2 + 27*NC*4)   // sVar + sPos + weights = 112256

// ---------------- device scratch (static; no runtime alloc) ----------------
__device__ __align__(16) float g_featT[(size_t)NV*NB*NHW*NC]; // (V,B,H,W,C)
__device__ float g_cost[(size_t)NB*ND*NHW];                   // (B,D,H,W)
__device__ float g_rot[NB][2][9];
__device__ float g_trans[NB][2][3];
__device__ float g_w[27*NC];                                  // [kd][kh][kw][c]
__device__ float g_bias;

// ---------------- prep: proj @ inv(ref_proj), weight relayout ----------------
__global__ void prep_kernel(const float* __restrict__ proj,
                            const float* __restrict__ rw,
                            const float* __restrict__ rb) {
    int tid = threadIdx.x;
    // relayout reg_w (1,C,3,3,3) -> [tap27][c]
    for (int i = tid; i < 27*NC; i += blockDim.x) {
        int cc = i / 27, k = i - cc*27;
        g_w[k*NC + cc] = rw[i];
    }
    if (tid == 0) g_bias = rb[0];
    if (tid < NB) {
        int b = tid;
        const float* refp = proj + ((size_t)b*NV + 0)*16;
        // Gauss-Jordan 4x4 inverse in double
        double a[4][8];
        for (int r = 0; r < 4; r++)
            for (int c2 = 0; c2 < 4; c2++) {
                a[r][c2] = (double)refp[r*4+c2];
                a[r][4+c2] = (r == c2) ? 1.0 : 0.0;
            }
        for (int col = 0; col < 4; col++) {
            int p = col; double best = fabs(a[col][col]);
            for (int r = col+1; r < 4; r++) {
                double v = fabs(a[r][col]);
                if (v > best) { best = v; p = r; }
            }
            if (p != col)
                for (int c2 = 0; c2 < 8; c2++) {
                    double t = a[col][c2]; a[col][c2] = a[p][c2]; a[p][c2] = t;
                }
            double pi = 1.0 / a[col][col];
            for (int c2 = 0; c2 < 8; c2++) a[col][c2] *= pi;
            for (int r = 0; r < 4; r++) if (r != col) {
                double f = a[r][col];
                for (int c2 = 0; c2 < 8; c2++) a[r][c2] -= f*a[col][c2];
            }
        }
        for (int v = 1; v < NV; v++) {
            const float* S = proj + ((size_t)b*NV + v)*16;
            for (int r = 0; r < 3; r++) {
                double pr[4];
                for (int c2 = 0; c2 < 4; c2++) {
                    double s = 0.0;
                    for (int k = 0; k < 4; k++) s += (double)S[r*4+k]*a[k][4+c2];
                    pr[c2] = s;
                }
                g_rot[b][v-1][r*3+0] = (float)pr[0];
                g_rot[b][v-1][r*3+1] = (float)pr[1];
                g_rot[b][v-1][r*3+2] = (float)pr[2];
                g_trans[b][v-1][r]   = (float)pr[3];
            }
        }
    }
}

// ---------------- transpose (V,B,C,H,W) -> (V,B,H,W,C) ----------------
__global__ void transpose_kernel(const float* __restrict__ feat) {
    __shared__ float t[32][33];
    int vb = blockIdx.y;
    int hw0 = blockIdx.x * 32;
    const float* src = feat + (size_t)vb*NC*NHW;
    #pragma unroll
    for (int cc = threadIdx.y; cc < 32; cc += 8)
        t[cc][threadIdx.x] = src[(size_t)cc*NHW + hw0 + threadIdx.x];
    __syncthreads();
    float* dst = g_featT + (size_t)vb*NHW*NC;
    #pragma unroll
    for (int r = threadIdx.y; r < 32; r += 8)
        dst[(size_t)(hw0 + r)*NC + threadIdx.x] = t[threadIdx.x][r];
}

// ---------------- bilinear sample of 4 channels (channel-last) ----------------
__device__ __forceinline__ void bilin4(const float* __restrict__ base, float px, float py,
                                       float& s0, float& s1, float& s2, float& s3,
                                       float& q0, float& q1, float& q2, float& q3) {
    float x0f = floorf(px), y0f = floorf(py);
    float wx1 = px - x0f, wy1 = py - y0f;
    float wx0 = 1.f - wx1, wy0 = 1.f - wy1;
    float x1f = x0f + 1.f, y1f = y0f + 1.f;
    float vx0 = (x0f >= 0.f && x0f <= (float)(NW-1)) ? 1.f : 0.f;
    float vx1 = (x1f >= 0.f && x1f <= (float)(NW-1)) ? 1.f : 0.f;
    float vy0 = (y0f >= 0.f && y0f <= (float)(NH-1)) ? 1.f : 0.f;
    float vy1 = (y1f >= 0.f && y1f <= (float)(NH-1)) ? 1.f : 0.f;
    int ix0 = (int)fminf(fmaxf(x0f, 0.f), (float)(NW-1));
    int ix1 = (int)fminf(fmaxf(x1f, 0.f), (float)(NW-1));
    int iy0 = (int)fminf(fmaxf(y0f, 0.f), (float)(NH-1));
    int iy1 = (int)fminf(fmaxf(y1f, 0.f), (float)(NH-1));
    float w00 = wx0*wy0*vx0*vy0;
    float w01 = wx1*wy0*vx1*vy0;
    float w10 = wx0*wy1*vx0*vy1;
    float w11 = wx1*wy1*vx1*vy1;
    const float4 f00 = __ldg((const float4*)(base + ((size_t)iy0*NW + ix0)*NC));
    const float4 f01 = __ldg((const float4*)(base + ((size_t)iy0*NW + ix1)*NC));
    const float4 f10 = __ldg((const float4*)(base + ((size_t)iy1*NW + ix0)*NC));
    const float4 f11 = __ldg((const float4*)(base + ((size_t)iy1*NW + ix1)*NC));
    float a0 = f00.x*w00 + f01.x*w01 + f10.x*w10 + f11.x*w11;
    float a1 = f00.y*w00 + f01.y*w01 + f10.y*w10 + f11.y*w11;
    float a2 = f00.z*w00 + f01.z*w01 + f10.z*w10 + f11.z*w11;
    float a3 = f00.w*w00 + f01.w*w01 + f10.w*w10 + f11.w*w11;
    s0 += a0; q0 += a0*a0;
    s1 += a1; q1 += a1*a1;
    s2 += a2; q2 += a2*a2;
    s3 += a3; q3 += a3*a3;
}

// ---------------- fused warp + variance + conv3d -> cost ----------------
__global__ __launch_bounds__(256, 2)
void fused_cost_kernel(const float* __restrict__ dvals) {
    extern __shared__ unsigned char smem_raw[];
    float4* sVar = (float4*)smem_raw;
    float4* sPos = sVar + NHALO;
    float*  sW   = (float*)(sPos + NHALO);

    const int tid = threadIdx.x;
    const int bz = blockIdx.z;
    const int b  = bz / (ND/TD);
    const int d0 = (bz - b*(ND/TD)) * TD;
    const int h0 = blockIdx.y * TH;
    const int w0 = blockIdx.x * TW;

    for (int i = tid; i < 27*NC; i += 256) sW[i] = g_w[i];

    float R[2][9], T[2][3];
    #pragma unroll
    for (int v = 0; v < 2; v++) {
        #pragma unroll
        for (int k = 0; k < 9; k++) R[v][k] = g_rot[b][v][k];
        #pragma unroll
        for (int k = 0; k < 3; k++) T[v][k] = g_trans[b][v][k];
    }

    // Phase 0: per-halo-point warped coords (shared across channel groups)
    for (int i = tid; i < NHALO; i += 256) {
        int dd = i / (HHs*HWs);
        int rem = i - dd*(HHs*HWs);
        int hh = rem / HWs;
        int ww = rem - hh*HWs;
        int d = d0 + dd - 1, h = h0 + hh - 1, w = w0 + ww - 1;
        float4 P = make_float4(-1e30f, -1e30f, -1e30f, -1e30f);
        if ((unsigned)d < (unsigned)ND && (unsigned)h < (unsigned)NH && (unsigned)w < (unsigned)NW) {
            float dep = __ldg(&dvals[b*ND + d]);
            float fx = (float)w, fy = (float)h;
            float res[4];
            #pragma unroll
            for (int v = 0; v < 2; v++) {
                float rx = R[v][0]*fx + R[v][1]*fy + R[v][2];
                float ry = R[v][3]*fx + R[v][4]*fy + R[v][5];
                float rz = R[v][6]*fx + R[v][7]*fy + R[v][8];
                float px = rx*dep + T[v][0];
                float py = ry*dep + T[v][1];
                float pz = rz*dep + T[v][2];
                if (fabsf(pz) < 1e-6f) pz = 1e-6f;
                res[v*2+0] = px / pz;
                res[v*2+1] = py / pz;
            }
            P = make_float4(res[0], res[1], res[2], res[3]);
        }
        sPos[i] = P;
    }
    __syncthreads();

    const int lw = tid & 31;
    const int lh = tid >> 5;
    float cost[TD];
    #pragma unroll
    for (int i = 0; i < TD; i++) cost[i] = 0.f;

    for (int cg = 0; cg < NC/4; cg++) {
        const int c0 = cg*4;
        // Phase A: variance for halo tile, 4 channels
        for (int i = tid; i < NHALO; i += 256) {
            int dd = i / (HHs*HWs);
            int rem = i - dd*(HHs*HWs);
            int hh = rem / HWs;
            int ww = rem - hh*HWs;
            int d = d0 + dd - 1, h = h0 + hh - 1, w = w0 + ww - 1;
            float4 var = make_float4(0.f, 0.f, 0.f, 0.f);
            if ((unsigned)d < (unsigned)ND && (unsigned)h < (unsigned)NH && (unsigned)w < (unsigned)NW) {
                const float4 r4 = __ldg((const float4*)(g_featT + ((size_t)b*NHW + h*NW + w)*NC + c0));
                float s0 = r4.x, s1 = r4.y, s2 = r4.z, s3 = r4.w;
                float q0 = r4.x*r4.x, q1 = r4.y*r4.y, q2 = r4.z*r4.z, q3 = r4.w*r4.w;
                float4 P = sPos[i];
                {
                    const float* base = g_featT + ((size_t)(1*NB + b)*NHW)*NC + c0;
                    bilin4(base, P.x, P.y, s0, s1, s2, s3, q0, q1, q2, q3);
                }
                {
                    const float* base = g_featT + ((size_t)(2*NB + b)*NHW)*NC + c0;
                    bilin4(base, P.z, P.w, s0, s1, s2, s3, q0, q1, q2, q3);
                }
                const float inv3 = (1.f/3.f);
                float m0 = s0*inv3, m1 = s1*inv3, m2 = s2*inv3, m3 = s3*inv3;
                var.x = q0*inv3 - m0*m0;
                var.y = q1*inv3 - m1*m1;
                var.z = q2*inv3 - m2*m2;
                var.w = q3*inv3 - m3*m3;
            }
            sVar[i] = var;
        }
        __syncthreads();

        // Phase B: 3^3 conv accumulation, weights in registers
        #pragma unroll
        for (int kh = 0; kh < 3; kh++) {
            #pragma unroll
            for (int kw = 0; kw < 3; kw++) {
                float wk[3][4];
                #pragma unroll
                for (int kd = 0; kd < 3; kd++) {
                    #pragma unroll
                    for (int cc = 0; cc < 4; cc++)
                        wk[kd][cc] = sW[((kd*3+kh)*3+kw)*NC + c0 + cc];
                }
                const float4* col = sVar + (lh+kh)*HWs + (lw+kw);
                #pragma unroll
                for (int dd = 0; dd < HD; dd++) {
                    float4 v = col[(size_t)dd*(HHs*HWs)];
                    #pragma unroll
                    for (int kd = 0; kd < 3; kd++) {
                        int lo = dd - kd;
                        if (lo >= 0 && lo < TD) {
                            cost[lo] += v.x*wk[kd][0] + v.y*wk[kd][1]
                                      + v.z*wk[kd][2] + v.w*wk[kd][3];
                        }
                    }
                }
            }
        }
        __syncthreads();
    }

    const float bias = g_bias;
    #pragma unroll
    for (int lo = 0; lo < TD; lo++) {
        g_cost[((size_t)b*ND + d0+lo)*NHW + (h0+lh)*NW + (w0+lw)] = cost[lo] + bias;
    }
}

// ---------------- softmax over depth + expected depth + confidence ----------------
__global__ __launch_bounds__(256)
void softmax_kernel(const float* __restrict__ dvals, float* __restrict__ out) {
    int gid = blockIdx.x*blockDim.x + threadIdx.x;
    if (gid >= NB*NHW) return;
    int b = gid / NHW;
    int hw = gid - b*NHW;
    const float* cp = g_cost + (size_t)b*ND*NHW + hw;
    float c[ND];
    float mx = -3.4e38f;
    #pragma unroll
    for (int d = 0; d < ND; d++) {
        c[d] = cp[(size_t)d*NHW];
        mx = fmaxf(mx, c[d]);
    }
    float sum = 0.f;
    #pragma unroll
    for (int d = 0; d < ND; d++) {
        c[d] = __expf(c[d] - mx);
        sum += c[d];
    }
    float inv = 1.f/sum;
    float depth = 0.f, fidx = 0.f;
    #pragma unroll
    for (int d = 0; d < ND; d++) {
        depth += c[d]*__ldg(&dvals[b*ND + d]);
        fidx  += c[d]*(float)d;
    }
    depth *= inv;
    fidx  *= inv;
    int di = (int)fidx;
    di = min(max(di, 0), ND-1);
    float conf = 0.f;
    #pragma unroll
    for (int d = 0; d < ND; d++) {
        if (d >= di-1 && d <= di+2) conf += c[d];
    }
    conf *= inv;
    out[gid] = depth;
    out[NB*NHW + gid] = conf;
}

// ---------------- launch ----------------
extern "C" void kernel_launch(void* const* d_in, const int* in_sizes, int n_in,
                              void* d_out, int out_size) {
    const float* features = (const float*)d_in[0];   // (V,B,C,H,W)
    const float* proj     = (const float*)d_in[1];   // (B,V,4,4)
    const float* dvals    = (const float*)d_in[2];   // (B,D)
    // locate reg_w (size 864) robustly; reg_b follows it
    int iw = 3;
    while (iw < n_in && in_sizes[iw] != 27*NC) iw++;
    const float* rw = (const float*)d_in[iw];
    const float* rb = (const float*)d_in[iw+1];

    cudaFuncSetAttribute(fused_cost_kernel,
                         cudaFuncAttributeMaxDynamicSharedMemorySize, SMEM_BYTES);

    prep_kernel<<<1, 256>>>(proj, rw, rb);
    transpose_kernel<<<dim3(NHW/32, NV*NB), dim3(32, 8)>>>(features);
    fused_cost_kernel<<<dim3(NW/TW, NH/TH, NB*(ND/TD)), 256, SMEM_BYTES>>>(dvals);
    softmax_kernel<<<(NB*NHW + 255)/256, 256>>>(dvals, (float*)d_out);
}

// round 2
// speedup vs baseline: 3.2914x; 3.2914x over previous
#include <cuda_runtime.h>
#include <cuda_bf16.h>
#include <math.h>

// ---------------- problem constants ----------------
#define NB 2
#define NV 3
#define NC 32
#define ND 48
#define NH 128
#define NW 160
#define NHW (NH*NW)          // 20480

// ---------------- fused kernel tiling ----------------
#define TD 8
#define TH 8
#define TW 32
#define HD (TD+2)            // 10
#define HHs (TH+2)           // 10
#define HWs (TW+2)           // 34
#define NHALO (HD*HHs*HWs)   // 3400
#define SMEM_BYTES (NHALO*16*2 + 27*NC*4)   // sVar + sPos + weights = 112256

// ---------------- device scratch (static; no runtime alloc) ----------------
// Feature staging layout: (V, B, CG=8, H, W, 4ch) -> pixel stride within a
// cg-plane is 16B, so a warp of adjacent pixels loads contiguously.
__device__ __align__(128) float g_featT[(size_t)NV*NB*NHW*NC];
__device__ float g_cost[(size_t)NB*ND*NHW];                   // (B,D,H,W)
__device__ float g_rot[NB][2][9];
__device__ float g_trans[NB][2][3];
__device__ float g_w[27*NC];                                  // [tap27][c]
__device__ float g_bias;

#define CG_PLANE ((size_t)NHW)              // float4 elements per cg-plane
#define VB_STRIDE ((size_t)8*NHW)           // float4 elements per (v,b)

// ---------------- prep: proj @ inv(ref_proj), weight relayout ----------------
__global__ void prep_kernel(const float* __restrict__ proj,
                            const float* __restrict__ rw,
                            const float* __restrict__ rb) {
    int tid = threadIdx.x;
    for (int i = tid; i < 27*NC; i += blockDim.x) {
        int cc = i / 27, k = i - cc*27;
        g_w[k*NC + cc] = rw[i];
    }
    if (tid == 0) g_bias = rb[0];
    if (tid < NB) {
        int b = tid;
        const float* refp = proj + ((size_t)b*NV + 0)*16;
        double a[4][8];
        for (int r = 0; r < 4; r++)
            for (int c2 = 0; c2 < 4; c2++) {
                a[r][c2] = (double)refp[r*4+c2];
                a[r][4+c2] = (r == c2) ? 1.0 : 0.0;
            }
        for (int col = 0; col < 4; col++) {
            int p = col; double best = fabs(a[col][col]);
            for (int r = col+1; r < 4; r++) {
                double v = fabs(a[r][col]);
                if (v > best) { best = v; p = r; }
            }
            if (p != col)
                for (int c2 = 0; c2 < 8; c2++) {
                    double t = a[col][c2]; a[col][c2] = a[p][c2]; a[p][c2] = t;
                }
            double pi = 1.0 / a[col][col];
            for (int c2 = 0; c2 < 8; c2++) a[col][c2] *= pi;
            for (int r = 0; r < 4; r++) if (r != col) {
                double f = a[r][col];
                for (int c2 = 0; c2 < 8; c2++) a[r][c2] -= f*a[col][c2];
            }
        }
        for (int v = 1; v < NV; v++) {
            const float* S = proj + ((size_t)b*NV + v)*16;
            for (int r = 0; r < 3; r++) {
                double pr[4];
                for (int c2 = 0; c2 < 4; c2++) {
                    double s = 0.0;
                    for (int k = 0; k < 4; k++) s += (double)S[r*4+k]*a[k][4+c2];
                    pr[c2] = s;
                }
                g_rot[b][v-1][r*3+0] = (float)pr[0];
                g_rot[b][v-1][r*3+1] = (float)pr[1];
                g_rot[b][v-1][r*3+2] = (float)pr[2];
                g_trans[b][v-1][r]   = (float)pr[3];
            }
        }
    }
}

// ---------------- transpose (V,B,C,H,W) -> (V,B,cg,H,W,4) ----------------
__global__ void transpose_kernel(const float* __restrict__ feat) {
    __shared__ float t[32][33];
    int vb = blockIdx.y;
    int hw0 = blockIdx.x * 32;
    const float* src = feat + (size_t)vb*NC*NHW;
    #pragma unroll
    for (int cc = threadIdx.y; cc < 32; cc += 8)
        t[cc][threadIdx.x] = src[(size_t)cc*NHW + hw0 + threadIdx.x];
    __syncthreads();
    float* dst = g_featT + (size_t)vb*VB_STRIDE*4;
    int c = threadIdx.x;
    int cg = c >> 2, c4 = c & 3;
    #pragma unroll
    for (int r = threadIdx.y; r < 32; r += 8)
        dst[((size_t)cg*CG_PLANE + hw0 + r)*4 + c4] = t[c][r];
}

// ---------------- bilinear sample of 4 channels (16B-stride pixels) ----------------
__device__ __forceinline__ void bilin4(const float4* __restrict__ base, float px, float py,
                                       float& s0, float& s1, float& s2, float& s3,
                                       float& q0, float& q1, float& q2, float& q3) {
    float x0f = floorf(px), y0f = floorf(py);
    float wx1 = px - x0f, wy1 = py - y0f;
    float wx0 = 1.f - wx1, wy0 = 1.f - wy1;
    float x1f = x0f + 1.f, y1f = y0f + 1.f;
    float vx0 = (x0f >= 0.f && x0f <= (float)(NW-1)) ? 1.f : 0.f;
    float vx1 = (x1f >= 0.f && x1f <= (float)(NW-1)) ? 1.f : 0.f;
    float vy0 = (y0f >= 0.f && y0f <= (float)(NH-1)) ? 1.f : 0.f;
    float vy1 = (y1f >= 0.f && y1f <= (float)(NH-1)) ? 1.f : 0.f;
    int ix0 = (int)fminf(fmaxf(x0f, 0.f), (float)(NW-1));
    int ix1 = (int)fminf(fmaxf(x1f, 0.f), (float)(NW-1));
    int iy0 = (int)fminf(fmaxf(y0f, 0.f), (float)(NH-1));
    int iy1 = (int)fminf(fmaxf(y1f, 0.f), (float)(NH-1));
    float w00 = wx0*wy0*vx0*vy0;
    float w01 = wx1*wy0*vx1*vy0;
    float w10 = wx0*wy1*vx0*vy1;
    float w11 = wx1*wy1*vx1*vy1;
    const float4 f00 = __ldg(base + (iy0*NW + ix0));
    const float4 f01 = __ldg(base + (iy0*NW + ix1));
    const float4 f10 = __ldg(base + (iy1*NW + ix0));
    const float4 f11 = __ldg(base + (iy1*NW + ix1));
    float a0 = f00.x*w00 + f01.x*w01 + f10.x*w10 + f11.x*w11;
    float a1 = f00.y*w00 + f01.y*w01 + f10.y*w10 + f11.y*w11;
    float a2 = f00.z*w00 + f01.z*w01 + f10.z*w10 + f11.z*w11;
    float a3 = f00.w*w00 + f01.w*w01 + f10.w*w10 + f11.w*w11;
    s0 += a0; q0 += a0*a0;
    s1 += a1; q1 += a1*a1;
    s2 += a2; q2 += a2*a2;
    s3 += a3; q3 += a3*a3;
}

// ---------------- fused warp + variance + conv3d -> cost ----------------
__global__ __launch_bounds__(256, 2)
void fused_cost_kernel(const float* __restrict__ dvals) {
    extern __shared__ unsigned char smem_raw[];
    float4* sVar = (float4*)smem_raw;
    float4* sPos = sVar + NHALO;
    float*  sW   = (float*)(sPos + NHALO);

    const int tid = threadIdx.x;
    const int bz = blockIdx.z;
    const int b  = bz / (ND/TD);
    const int d0 = (bz - b*(ND/TD)) * TD;
    const int h0 = blockIdx.y * TH;
    const int w0 = blockIdx.x * TW;

    for (int i = tid; i < 27*NC; i += 256) sW[i] = g_w[i];

    float R[2][9], T[2][3];
    #pragma unroll
    for (int v = 0; v < 2; v++) {
        #pragma unroll
        for (int k = 0; k < 9; k++) R[v][k] = g_rot[b][v][k];
        #pragma unroll
        for (int k = 0; k < 3; k++) T[v][k] = g_trans[b][v][k];
    }

    // Phase 0: per-halo-point warped coords (shared across channel groups)
    for (int i = tid; i < NHALO; i += 256) {
        int dd = i / (HHs*HWs);
        int rem = i - dd*(HHs*HWs);
        int hh = rem / HWs;
        int ww = rem - hh*HWs;
        int d = d0 + dd - 1, h = h0 + hh - 1, w = w0 + ww - 1;
        float4 P = make_float4(-1e30f, -1e30f, -1e30f, -1e30f);
        if ((unsigned)d < (unsigned)ND && (unsigned)h < (unsigned)NH && (unsigned)w < (unsigned)NW) {
            float dep = __ldg(&dvals[b*ND + d]);
            float fx = (float)w, fy = (float)h;
            float res[4];
            #pragma unroll
            for (int v = 0; v < 2; v++) {
                float rx = R[v][0]*fx + R[v][1]*fy + R[v][2];
                float ry = R[v][3]*fx + R[v][4]*fy + R[v][5];
                float rz = R[v][6]*fx + R[v][7]*fy + R[v][8];
                float px = rx*dep + T[v][0];
                float py = ry*dep + T[v][1];
                float pz = rz*dep + T[v][2];
                if (fabsf(pz) < 1e-6f) pz = 1e-6f;
                res[v*2+0] = px / pz;
                res[v*2+1] = py / pz;
            }
            P = make_float4(res[0], res[1], res[2], res[3]);
        }
        sPos[i] = P;
    }
    __syncthreads();

    const int lw = tid & 31;
    const int lh = tid >> 5;
    float cost[TD];
    #pragma unroll
    for (int i = 0; i < TD; i++) cost[i] = 0.f;

    for (int cg = 0; cg < NC/4; cg++) {
        const float4* refBase = (const float4*)g_featT + ((size_t)(0*NB + b)*VB_STRIDE + (size_t)cg*CG_PLANE);
        const float4* v1Base  = (const float4*)g_featT + ((size_t)(1*NB + b)*VB_STRIDE + (size_t)cg*CG_PLANE);
        const float4* v2Base  = (const float4*)g_featT + ((size_t)(2*NB + b)*VB_STRIDE + (size_t)cg*CG_PLANE);

        // Phase A: variance for halo tile, 4 channels (coalesced: 16B pixel stride)
        for (int i = tid; i < NHALO; i += 256) {
            int dd = i / (HHs*HWs);
            int rem = i - dd*(HHs*HWs);
            int hh = rem / HWs;
            int ww = rem - hh*HWs;
            int d = d0 + dd - 1, h = h0 + hh - 1, w = w0 + ww - 1;
            float4 var = make_float4(0.f, 0.f, 0.f, 0.f);
            if ((unsigned)d < (unsigned)ND && (unsigned)h < (unsigned)NH && (unsigned)w < (unsigned)NW) {
                const float4 r4 = __ldg(refBase + (h*NW + w));
                float s0 = r4.x, s1 = r4.y, s2 = r4.z, s3 = r4.w;
                float q0 = r4.x*r4.x, q1 = r4.y*r4.y, q2 = r4.z*r4.z, q3 = r4.w*r4.w;
                float4 P = sPos[i];
                bilin4(v1Base, P.x, P.y, s0, s1, s2, s3, q0, q1, q2, q3);
                bilin4(v2Base, P.z, P.w, s0, s1, s2, s3, q0, q1, q2, q3);
                const float inv3 = (1.f/3.f);
                float m0 = s0*inv3, m1 = s1*inv3, m2 = s2*inv3, m3 = s3*inv3;
                var.x = q0*inv3 - m0*m0;
                var.y = q1*inv3 - m1*m1;
                var.z = q2*inv3 - m2*m2;
                var.w = q3*inv3 - m3*m3;
            }
            sVar[i] = var;
        }
        __syncthreads();

        // Phase B: 3^3 conv accumulation, weights in registers
        const int c0 = cg*4;
        #pragma unroll
        for (int kh = 0; kh < 3; kh++) {
            #pragma unroll
            for (int kw = 0; kw < 3; kw++) {
                float wk[3][4];
                #pragma unroll
                for (int kd = 0; kd < 3; kd++) {
                    #pragma unroll
                    for (int cc = 0; cc < 4; cc++)
                        wk[kd][cc] = sW[((kd*3+kh)*3+kw)*NC + c0 + cc];
                }
                const float4* col = sVar + (lh+kh)*HWs + (lw+kw);
                #pragma unroll
                for (int dd = 0; dd < HD; dd++) {
                    float4 v = col[(size_t)dd*(HHs*HWs)];
                    #pragma unroll
                    for (int kd = 0; kd < 3; kd++) {
                        int lo = dd - kd;
                        if (lo >= 0 && lo < TD) {
                            cost[lo] += v.x*wk[kd][0] + v.y*wk[kd][1]
                                      + v.z*wk[kd][2] + v.w*wk[kd][3];
                        }
                    }
                }
            }
        }
        __syncthreads();
    }

    const float bias = g_bias;
    #pragma unroll
    for (int lo = 0; lo < TD; lo++) {
        g_cost[((size_t)b*ND + d0+lo)*NHW + (h0+lh)*NW + (w0+lw)] = cost[lo] + bias;
    }
}

// ---------------- softmax over depth + expected depth + confidence ----------------
__global__ __launch_bounds__(256)
void softmax_kernel(const float* __restrict__ dvals, float* __restrict__ out) {
    int gid = blockIdx.x*blockDim.x + threadIdx.x;
    if (gid >= NB*NHW) return;
    int b = gid / NHW;
    int hw = gid - b*NHW;
    const float* cp = g_cost + (size_t)b*ND*NHW + hw;
    float c[ND];
    float mx = -3.4e38f;
    #pragma unroll
    for (int d = 0; d < ND; d++) {
        c[d] = cp[(size_t)d*NHW];
        mx = fmaxf(mx, c[d]);
    }
    float sum = 0.f;
    #pragma unroll
    for (int d = 0; d < ND; d++) {
        c[d] = __expf(c[d] - mx);
        sum += c[d];
    }
    float inv = 1.f/sum;
    float depth = 0.f, fidx = 0.f;
    #pragma unroll
    for (int d = 0; d < ND; d++) {
        depth += c[d]*__ldg(&dvals[b*ND + d]);
        fidx  += c[d]*(float)d;
    }
    depth *= inv;
    fidx  *= inv;
    int di = (int)fidx;
    di = min(max(di, 0), ND-1);
    float conf = 0.f;
    #pragma unroll
    for (int d = 0; d < ND; d++) {
        if (d >= di-1 && d <= di+2) conf += c[d];
    }
    conf *= inv;
    out[gid] = depth;
    out[NB*NHW + gid] = conf;
}

// ---------------- launch ----------------
extern "C" void kernel_launch(void* const* d_in, const int* in_sizes, int n_in,
                              void* d_out, int out_size) {
    const float* features = (const float*)d_in[0];   // (V,B,C,H,W)
    const float* proj     = (const float*)d_in[1];   // (B,V,4,4)
    const float* dvals    = (const float*)d_in[2];   // (B,D)
    int iw = 3;
    while (iw < n_in && in_sizes[iw] != 27*NC) iw++;
    const float* rw = (const float*)d_in[iw];
    const float* rb = (const float*)d_in[iw+1];

    cudaFuncSetAttribute(fused_cost_kernel,
                         cudaFuncAttributeMaxDynamicSharedMemorySize, SMEM_BYTES);

    prep_kernel<<<1, 256>>>(proj, rw, rb);
    transpose_kernel<<<dim3(NHW/32, NV*NB), dim3(32, 8)>>>(features);
    fused_cost_kernel<<<dim3(NW/TW, NH/TH, NB*(ND/TD)), 256, SMEM_BYTES>>>(dvals);
    softmax_kernel<<<(NB*NHW + 255)/256, 256>>>(dvals, (float*)d_out);
}